// round 11
// baseline (speedup 1.0000x reference)
#include <cuda_runtime.h>
#include <cuda_fp16.h>
#include <cstdint>

// Problem constants: B=2, S=2048, H=1024, N=16, HN=64
#define BB 2
#define SS 2048
#define HH 1024
#define NH 16
#define HD 64
#define MROWS (BB*SS)          // 4096
#define QKV_N (3*HH)           // 3072

// Device scratch (allocation-free rule -> __device__ globals), fp16
__device__ __half g_q[BB*NH*SS*HD];    // pre-scaled by 0.125*log2(e)
__device__ __half g_k[BB*NH*SS*HD];
__device__ __half g_v[BB*NH*SS*HD];
__device__ __half g_ctx[MROWS*HH];
__device__ __half g_hs[MROWS*HH];      // fp16 hidden_states
__device__ __half g_wqkv[HH*QKV_N];    // fp16 w_qkv [k][n]
__device__ __half g_wd[HH*HH];         // fp16 w_dense [k][n]

// ---------------------------------------------------------------------------
// helpers
// ---------------------------------------------------------------------------
__device__ __forceinline__ void mma_f16(float* d, const unsigned* a, const unsigned* b) {
    asm volatile(
        "mma.sync.aligned.m16n8k16.row.col.f32.f16.f16.f32 "
        "{%0,%1,%2,%3}, {%4,%5,%6,%7}, {%8,%9}, {%0,%1,%2,%3};"
        : "+f"(d[0]), "+f"(d[1]), "+f"(d[2]), "+f"(d[3])
        : "r"(a[0]), "r"(a[1]), "r"(a[2]), "r"(a[3]), "r"(b[0]), "r"(b[1]));
}
__device__ __forceinline__ void ldsm4(unsigned& r0, unsigned& r1, unsigned& r2, unsigned& r3,
                                      const void* p) {
    unsigned addr = (unsigned)__cvta_generic_to_shared(p);
    asm volatile("ldmatrix.sync.aligned.m8n8.x4.shared.b16 {%0,%1,%2,%3}, [%4];"
                 : "=r"(r0), "=r"(r1), "=r"(r2), "=r"(r3) : "r"(addr));
}
__device__ __forceinline__ void ldsm4t(unsigned& r0, unsigned& r1, unsigned& r2, unsigned& r3,
                                       const void* p) {
    unsigned addr = (unsigned)__cvta_generic_to_shared(p);
    asm volatile("ldmatrix.sync.aligned.m8n8.x4.trans.shared.b16 {%0,%1,%2,%3}, [%4];"
                 : "=r"(r0), "=r"(r1), "=r"(r2), "=r"(r3) : "r"(addr));
}
__device__ __forceinline__ void cpa16(void* dst, const void* src) {
    unsigned d = (unsigned)__cvta_generic_to_shared(dst);
    asm volatile("cp.async.cg.shared.global [%0], [%1], 16;" :: "r"(d), "l"(src));
}
__device__ __forceinline__ void cp_commit() { asm volatile("cp.async.commit_group;"); }

__device__ __forceinline__ unsigned pack_h2(float a, float b) {
    __half2 h = __floats2half2_rn(a, b);
    return *reinterpret_cast<unsigned*>(&h);
}

// ---------------------------------------------------------------------------
// fp32 -> fp16 conversion (one-time)
// ---------------------------------------------------------------------------
__global__ __launch_bounds__(256) void f2h_kernel(const float* __restrict__ in,
                                                  __half* __restrict__ out, int n) {
    int i = (blockIdx.x * 256 + threadIdx.x) * 8;
    if (i >= n) return;
    float4 a = *reinterpret_cast<const float4*>(in + i);
    float4 b = *reinterpret_cast<const float4*>(in + i + 4);
    __half2 h[4] = { __floats2half2_rn(a.x, a.y), __floats2half2_rn(a.z, a.w),
                     __floats2half2_rn(b.x, b.y), __floats2half2_rn(b.z, b.w) };
    *reinterpret_cast<float4*>(out + i) = *reinterpret_cast<float4*>(h);
}

// ---------------------------------------------------------------------------
// fp16 GEMM (R7/R10 best, unchanged except q pre-scale constant):
// C[M,Nn] = A[M,K] @ B[K,Nn] + bias. Block 128x128, BK=64, 2-stage cp.async.
// mode 0: write float C. mode 1: scatter half into g_q/g_k/g_v.
// ---------------------------------------------------------------------------
#define GBK 64
#define GLDA 72
#define GLDB 136
#define GA_ST (128 * GLDA)
#define GB_ST (GBK * GLDB)
#define GEMM_SMEM ((2 * GA_ST + 2 * GB_ST) * 2)   // 71680 B -> 2 CTAs/SM
#define QSCALE 0.1803368801111244f                 // 0.125 * log2(e)

__global__ __launch_bounds__(256) void gemm_f16(
    const __half* __restrict__ A, const __half* __restrict__ Bm,
    const float* __restrict__ bias, float* __restrict__ C,
    int Nn, int Kk, int mode)
{
    extern __shared__ __half gsm[];
    __half* As = gsm;                      // [2][128][GLDA]
    __half* Bs = gsm + 2 * GA_ST;          // [2][GBK][GLDB]

    int tid = threadIdx.x;
    int wid = tid >> 5, lane = tid & 31;
    int g = lane >> 2, t = lane & 3;
    int wm = wid & 3, wn = wid >> 2;
    int bx = blockIdx.x, by = blockIdx.y;

    const __half* Ab = A + (size_t)by * 128 * Kk;
    const __half* Bb = Bm + (size_t)bx * 128;

    float acc[2][8][4];
    #pragma unroll
    for (int mi = 0; mi < 2; ++mi)
        #pragma unroll
        for (int ni = 0; ni < 8; ++ni)
            #pragma unroll
            for (int c = 0; c < 4; ++c) acc[mi][ni][c] = 0.f;

    int a_r = lane & 15, a_c8 = (lane >> 4) << 3;
    int b_r = ((lane >> 3) & 1) * 8 + (lane & 7);
    int b_c8 = (lane >> 4) << 3;

    int ar[4], ac[4], br_[4], bc[4];
    #pragma unroll
    for (int it = 0; it < 4; ++it) {
        int idx = tid + it * 256;
        ar[it] = idx >> 3;  ac[it] = (idx & 7) << 3;
        br_[it] = idx >> 4; bc[it] = (idx & 15) << 3;
    }

    const int nk = Kk / GBK;

    auto prefetch = [&](int kt) {
        int st = kt & 1;
        __half* Ad = As + st * GA_ST;
        __half* Bd = Bs + st * GB_ST;
        int k0 = kt * GBK;
        #pragma unroll
        for (int it = 0; it < 4; ++it) {
            cpa16(&Ad[ar[it] * GLDA + ac[it]], Ab + (size_t)ar[it] * Kk + k0 + ac[it]);
            cpa16(&Bd[br_[it] * GLDB + bc[it]], Bb + (size_t)(k0 + br_[it]) * Nn + bc[it]);
        }
        cp_commit();
    };

    prefetch(0);

    for (int kt = 0; kt < nk; ++kt) {
        int st = kt & 1;
        asm volatile("cp.async.wait_group 0;");
        __syncthreads();
        if (kt + 1 < nk) prefetch(kt + 1);

        const __half* Ac = As + st * GA_ST;
        const __half* Bc = Bs + st * GB_ST;
        #pragma unroll
        for (int ks = 0; ks < 4; ++ks) {
            int kk = ks * 16;
            unsigned a[2][4], b[8][2];
            #pragma unroll
            for (int mi = 0; mi < 2; ++mi)
                ldsm4(a[mi][0], a[mi][1], a[mi][2], a[mi][3],
                      &Ac[(wm * 32 + mi * 16 + a_r) * GLDA + kk + a_c8]);
            #pragma unroll
            for (int p = 0; p < 4; ++p) {
                unsigned r0, r1, r2, r3;
                ldsm4t(r0, r1, r2, r3, &Bc[(kk + b_r) * GLDB + wn * 64 + p * 16 + b_c8]);
                b[2 * p][0] = r0; b[2 * p][1] = r1;
                b[2 * p + 1][0] = r2; b[2 * p + 1][1] = r3;
            }
            #pragma unroll
            for (int mi = 0; mi < 2; ++mi)
                #pragma unroll
                for (int ni = 0; ni < 8; ++ni)
                    mma_f16(acc[mi][ni], a[mi], b[ni]);
        }
    }

    // Epilogue
    #pragma unroll
    for (int mi = 0; mi < 2; ++mi) {
        int r0 = by * 128 + wm * 32 + mi * 16 + g;
        #pragma unroll
        for (int ni = 0; ni < 8; ++ni) {
            int c0 = bx * 128 + wn * 64 + ni * 8 + t * 2;
            float v00 = acc[mi][ni][0] + bias[c0];
            float v01 = acc[mi][ni][1] + bias[c0 + 1];
            float v10 = acc[mi][ni][2] + bias[c0];
            float v11 = acc[mi][ni][3] + bias[c0 + 1];
            if (mode == 0) {
                C[(size_t)r0 * Nn + c0]           = v00;
                C[(size_t)r0 * Nn + c0 + 1]       = v01;
                C[(size_t)(r0 + 8) * Nn + c0]     = v10;
                C[(size_t)(r0 + 8) * Nn + c0 + 1] = v11;
            } else {
                #pragma unroll
                for (int e = 0; e < 4; ++e) {
                    int rr = r0 + (e >> 1) * 8;
                    int cc = c0 + (e & 1);
                    float v = (e == 0) ? v00 : (e == 1) ? v01 : (e == 2) ? v10 : v11;
                    int b_ = rr >> 11, s_ = rr & 2047;
                    int which = cc >> 10, h = cc & 1023;
                    int n = h >> 6, d = h & 63;
                    size_t dst = ((size_t)(b_ * NH + n) * SS + s_) * HD + d;
                    if (which == 0)       g_q[dst] = __float2half(v * QSCALE);
                    else if (which == 1)  g_k[dst] = __float2half(v);
                    else                  g_v[dst] = __float2half(v);
                }
            }
        }
    }
}

// ---------------------------------------------------------------------------
// Causal flash attention: warp tile m32 (2x K/V ldmatrix reuse), FA2 register
// P-reuse, hoisted Q frags, exp2 softmax (log2e folded into q scale).
// CTA: 128 threads (4 warps), 128 q-rows (32 per warp), 64-key tiles,
// cp.async double-buffered K/V. smem: Qs[128][72] + K/V[2][64][72] = 55296 B.
// ---------------------------------------------------------------------------
#define ALD 72
#define AT_ST (64 * ALD)
#define AQ_ST (128 * ALD)
#define ATTN_SMEM ((AQ_ST + 4 * AT_ST) * 2)

__global__ __launch_bounds__(128, 2) void attn_f16() {
    extern __shared__ __half asm_[];
    __half* Qs = asm_;                     // [128][ALD]
    __half* Ks = asm_ + AQ_ST;             // [2][64][ALD]
    __half* Vs = asm_ + AQ_ST + 2 * AT_ST; // [2][64][ALD]

    int qb = (gridDim.x - 1) - blockIdx.x; // heavy q-blocks launch first
    int bn = blockIdx.y;
    const __half* Qp = g_q + (size_t)bn * SS * HD;
    const __half* Kp = g_k + (size_t)bn * SS * HD;
    const __half* Vp = g_v + (size_t)bn * SS * HD;

    int tid = threadIdx.x;
    int wid = tid >> 5, lane = tid & 31;
    int g = lane >> 2, t = lane & 3;
    int row0 = wid * 32;                   // warp's 32 q-rows within CTA block
    int qrow0 = qb * 128 + row0;           // global

    int a_r = lane & 15, a_c8 = (lane >> 4) << 3;
    int kb_r = ((lane >> 4) & 1) * 8 + (lane & 7);
    int kb_c8 = ((lane >> 3) & 1) * 8;
    int vb_r = ((lane >> 3) & 1) * 8 + (lane & 7);
    int vb_c8 = (lane >> 4) << 3;

    // cp.async coords: K/V 64 rows x 8 chunks = 512 / 128 thr = 4 per thread
    int cr[4], cc_[4];
    #pragma unroll
    for (int it = 0; it < 4; ++it) {
        int idx = tid + it * 128;
        cr[it] = idx >> 3; cc_[it] = (idx & 7) << 3;
    }

    auto prefetch_kv = [&](int j) {
        int st = j & 1;
        const __half* Kn = Kp + (size_t)j * 64 * HD;
        const __half* Vn = Vp + (size_t)j * 64 * HD;
        __half* Kd = Ks + st * AT_ST;
        __half* Vd = Vs + st * AT_ST;
        #pragma unroll
        for (int it = 0; it < 4; ++it) {
            cpa16(&Kd[cr[it] * ALD + cc_[it]], Kn + (size_t)cr[it] * HD + cc_[it]);
            cpa16(&Vd[cr[it] * ALD + cc_[it]], Vn + (size_t)cr[it] * HD + cc_[it]);
        }
        cp_commit();
    };

    prefetch_kv(0);

    // Q tile: 128 rows x 8 chunks = 1024, 8 per thread (plain loads)
    #pragma unroll
    for (int it = 0; it < 8; ++it) {
        int idx = tid + it * 128;
        int r = idx >> 3, c8 = (idx & 7) << 3;
        float4 v = *reinterpret_cast<const float4*>(Qp + (size_t)(qb * 128 + r) * HD + c8);
        *reinterpret_cast<float4*>(&Qs[r * ALD + c8]) = v;
    }
    __syncthreads();

    // Hoist Q fragments (2 m-subtiles x 4 k-chunks)
    unsigned qa[2][4][4];
    #pragma unroll
    for (int mi = 0; mi < 2; ++mi)
        #pragma unroll
        for (int ks = 0; ks < 4; ++ks)
            ldsm4(qa[mi][ks][0], qa[mi][ks][1], qa[mi][ks][2], qa[mi][ks][3],
                  &Qs[(row0 + mi * 16 + a_r) * ALD + ks * 16 + a_c8]);

    float accO[2][8][4];
    #pragma unroll
    for (int mi = 0; mi < 2; ++mi)
        #pragma unroll
        for (int ni = 0; ni < 8; ++ni)
            #pragma unroll
            for (int c = 0; c < 4; ++c) accO[mi][ni][c] = 0.f;
    float mr[2][2] = {{-1e30f, -1e30f}, {-1e30f, -1e30f}};
    float lr[2][2] = {{0.f, 0.f}, {0.f, 0.f}};

    const int jmax = 2 * qb + 1;
    for (int j = 0; j <= jmax; ++j) {
        int st = j & 1;
        asm volatile("cp.async.wait_group 0;");
        __syncthreads();
        if (j < jmax) prefetch_kv(j + 1);

        if ((qrow0 + 31) < j * 64) continue;   // warp fully masked

        const __half* Kc = Ks + st * AT_ST;
        const __half* Vc = Vs + st * AT_ST;

        // S = Q @ K^T (both m-subtiles share each K fragment)
        float s[2][8][4];
        #pragma unroll
        for (int mi = 0; mi < 2; ++mi)
            #pragma unroll
            for (int ni = 0; ni < 8; ++ni)
                #pragma unroll
                for (int c = 0; c < 4; ++c) s[mi][ni][c] = 0.f;

        #pragma unroll
        for (int ks = 0; ks < 4; ++ks) {
            int kk = ks * 16;
            #pragma unroll
            for (int p = 0; p < 4; ++p) {
                unsigned r0, r1, r2, r3;
                ldsm4(r0, r1, r2, r3, &Kc[(p * 16 + kb_r) * ALD + kk + kb_c8]);
                unsigned b0[2] = {r0, r1}, b1[2] = {r2, r3};
                mma_f16(s[0][2 * p],     qa[0][ks], b0);
                mma_f16(s[0][2 * p + 1], qa[0][ks], b1);
                mma_f16(s[1][2 * p],     qa[1][ks], b0);
                mma_f16(s[1][2 * p + 1], qa[1][ks], b1);
            }
        }

        // causal mask (global indices) on diagonal-touching tiles
        if (j * 64 + 63 > qrow0) {
            #pragma unroll
            for (int mi = 0; mi < 2; ++mi)
                #pragma unroll
                for (int ni = 0; ni < 8; ++ni) {
                    int c0 = j * 64 + ni * 8 + t * 2;
                    int r0a = qrow0 + mi * 16 + g, r1a = r0a + 8;
                    if (c0     > r0a) s[mi][ni][0] = -1e30f;
                    if (c0 + 1 > r0a) s[mi][ni][1] = -1e30f;
                    if (c0     > r1a) s[mi][ni][2] = -1e30f;
                    if (c0 + 1 > r1a) s[mi][ni][3] = -1e30f;
                }
        }

        // online softmax (base-2; log2e folded into q)
        #pragma unroll
        for (int mi = 0; mi < 2; ++mi) {
            float mx0 = -1e30f, mx1 = -1e30f;
            #pragma unroll
            for (int ni = 0; ni < 8; ++ni) {
                mx0 = fmaxf(mx0, fmaxf(s[mi][ni][0], s[mi][ni][1]));
                mx1 = fmaxf(mx1, fmaxf(s[mi][ni][2], s[mi][ni][3]));
            }
            mx0 = fmaxf(mx0, __shfl_xor_sync(0xffffffffu, mx0, 1));
            mx0 = fmaxf(mx0, __shfl_xor_sync(0xffffffffu, mx0, 2));
            mx1 = fmaxf(mx1, __shfl_xor_sync(0xffffffffu, mx1, 1));
            mx1 = fmaxf(mx1, __shfl_xor_sync(0xffffffffu, mx1, 2));

            float mn0 = fmaxf(mr[mi][0], mx0), mn1 = fmaxf(mr[mi][1], mx1);
            float corr0 = exp2f(mr[mi][0] - mn0), corr1 = exp2f(mr[mi][1] - mn1);
            float sum0 = 0.f, sum1 = 0.f;
            #pragma unroll
            for (int ni = 0; ni < 8; ++ni) {
                s[mi][ni][0] = exp2f(s[mi][ni][0] - mn0);
                s[mi][ni][1] = exp2f(s[mi][ni][1] - mn0);
                s[mi][ni][2] = exp2f(s[mi][ni][2] - mn1);
                s[mi][ni][3] = exp2f(s[mi][ni][3] - mn1);
                sum0 += s[mi][ni][0] + s[mi][ni][1];
                sum1 += s[mi][ni][2] + s[mi][ni][3];
            }
            sum0 += __shfl_xor_sync(0xffffffffu, sum0, 1);
            sum0 += __shfl_xor_sync(0xffffffffu, sum0, 2);
            sum1 += __shfl_xor_sync(0xffffffffu, sum1, 1);
            sum1 += __shfl_xor_sync(0xffffffffu, sum1, 2);
            lr[mi][0] = lr[mi][0] * corr0 + sum0;
            lr[mi][1] = lr[mi][1] * corr1 + sum1;
            mr[mi][0] = mn0; mr[mi][1] = mn1;
            #pragma unroll
            for (int ni = 0; ni < 8; ++ni) {
                accO[mi][ni][0] *= corr0; accO[mi][ni][1] *= corr0;
                accO[mi][ni][2] *= corr1; accO[mi][ni][3] *= corr1;
            }
        }

        // O += P @ V (register P; both m-subtiles share each V fragment)
        #pragma unroll
        for (int p = 0; p < 4; ++p) {
            unsigned pa0[4], pa1[4];
            pa0[0] = pack_h2(s[0][2 * p][0],     s[0][2 * p][1]);
            pa0[1] = pack_h2(s[0][2 * p][2],     s[0][2 * p][3]);
            pa0[2] = pack_h2(s[0][2 * p + 1][0], s[0][2 * p + 1][1]);
            pa0[3] = pack_h2(s[0][2 * p + 1][2], s[0][2 * p + 1][3]);
            pa1[0] = pack_h2(s[1][2 * p][0],     s[1][2 * p][1]);
            pa1[1] = pack_h2(s[1][2 * p][2],     s[1][2 * p][3]);
            pa1[2] = pack_h2(s[1][2 * p + 1][0], s[1][2 * p + 1][1]);
            pa1[3] = pack_h2(s[1][2 * p + 1][2], s[1][2 * p + 1][3]);
            int kk = p * 16;
            #pragma unroll
            for (int q = 0; q < 4; ++q) {
                unsigned r0, r1, r2, r3;
                ldsm4t(r0, r1, r2, r3, &Vc[(kk + vb_r) * ALD + q * 16 + vb_c8]);
                unsigned b0[2] = {r0, r1}, b1[2] = {r2, r3};
                mma_f16(accO[0][2 * q],     pa0, b0);
                mma_f16(accO[0][2 * q + 1], pa0, b1);
                mma_f16(accO[1][2 * q],     pa1, b0);
                mma_f16(accO[1][2 * q + 1], pa1, b1);
            }
        }
    }

    // Finalize: write ctx (half) in [b*s, h] layout
    int b_ = bn >> 4, n = bn & 15;
    #pragma unroll
    for (int mi = 0; mi < 2; ++mi) {
        float inv0 = 1.0f / lr[mi][0], inv1 = 1.0f / lr[mi][1];
        int s0 = qb * 128 + row0 + mi * 16 + g;
        int s1 = s0 + 8;
        #pragma unroll
        for (int ni = 0; ni < 8; ++ni) {
            int c0 = n * HD + ni * 8 + t * 2;
            *reinterpret_cast<__half2*>(&g_ctx[((size_t)b_ * SS + s0) * HH + c0]) =
                __floats2half2_rn(accO[mi][ni][0] * inv0, accO[mi][ni][1] * inv0);
            *reinterpret_cast<__half2*>(&g_ctx[((size_t)b_ * SS + s1) * HH + c0]) =
                __floats2half2_rn(accO[mi][ni][2] * inv1, accO[mi][ni][3] * inv1);
        }
    }
}

// ---------------------------------------------------------------------------
extern "C" void kernel_launch(void* const* d_in, const int* in_sizes, int n_in,
                              void* d_out, int out_size) {
    const float* hs      = (const float*)d_in[0];
    const float* w_qkv   = (const float*)d_in[2];
    const float* b_qkv   = (const float*)d_in[3];
    const float* w_dense = (const float*)d_in[4];
    const float* b_dense = (const float*)d_in[5];
    float* out = (float*)d_out;

    void *hs_h, *wqkv_h, *wd_h, *ctx_h;
    cudaGetSymbolAddress(&hs_h, g_hs);
    cudaGetSymbolAddress(&wqkv_h, g_wqkv);
    cudaGetSymbolAddress(&wd_h, g_wd);
    cudaGetSymbolAddress(&ctx_h, g_ctx);

    cudaFuncSetAttribute(gemm_f16, cudaFuncAttributeMaxDynamicSharedMemorySize, GEMM_SMEM);
    cudaFuncSetAttribute(attn_f16, cudaFuncAttributeMaxDynamicSharedMemorySize, ATTN_SMEM);

    // 0) fp32 -> fp16 conversions
    f2h_kernel<<<(MROWS * HH) / (256 * 8), 256>>>(hs, (__half*)hs_h, MROWS * HH);
    f2h_kernel<<<(HH * QKV_N) / (256 * 8), 256>>>(w_qkv, (__half*)wqkv_h, HH * QKV_N);
    f2h_kernel<<<(HH * HH) / (256 * 8), 256>>>(w_dense, (__half*)wd_h, HH * HH);

    // 1) QKV projection with head-layout scatter (q pre-scaled by 0.125*log2e)
    dim3 g1(QKV_N / 128, MROWS / 128);   // (24, 32)
    gemm_f16<<<g1, 256, GEMM_SMEM>>>((const __half*)hs_h, (const __half*)wqkv_h,
                                     b_qkv, nullptr, QKV_N, HH, 1);

    // 2) Causal flash attention (128 q-rows per CTA, m32 warp tiles)
    dim3 g2(SS / 128, BB * NH);          // (16, 32)
    attn_f16<<<g2, 128, ATTN_SMEM>>>();

    // 3) Output projection
    dim3 g3(HH / 128, MROWS / 128);      // (8, 32)
    gemm_f16<<<g3, 256, GEMM_SMEM>>>((const __half*)ctx_h, (const __half*)wd_h,
                                     b_dense, out, HH, HH, 0);
}

// round 12
// speedup vs baseline: 1.0900x; 1.0900x over previous
#include <cuda_runtime.h>
#include <cuda_fp16.h>
#include <cstdint>

// Problem constants: B=2, S=2048, H=1024, N=16, HN=64
#define BB 2
#define SS 2048
#define HH 1024
#define NH 16
#define HD 64
#define MROWS (BB*SS)          // 4096
#define QKV_N (3*HH)           // 3072

// Device scratch (allocation-free rule -> __device__ globals), fp16
__device__ __half g_q[BB*NH*SS*HD];    // pre-scaled by 0.125*log2(e)
__device__ __half g_k[BB*NH*SS*HD];
__device__ __half g_v[BB*NH*SS*HD];
__device__ __half g_ctx[MROWS*HH];
__device__ __half g_hs[MROWS*HH];      // fp16 hidden_states
__device__ __half g_wqkv[HH*QKV_N];    // fp16 w_qkv [k][n]
__device__ __half g_wd[HH*HH];         // fp16 w_dense [k][n]

// ---------------------------------------------------------------------------
// helpers
// ---------------------------------------------------------------------------
__device__ __forceinline__ void mma_f16(float* d, const unsigned* a, const unsigned* b) {
    asm volatile(
        "mma.sync.aligned.m16n8k16.row.col.f32.f16.f16.f32 "
        "{%0,%1,%2,%3}, {%4,%5,%6,%7}, {%8,%9}, {%0,%1,%2,%3};"
        : "+f"(d[0]), "+f"(d[1]), "+f"(d[2]), "+f"(d[3])
        : "r"(a[0]), "r"(a[1]), "r"(a[2]), "r"(a[3]), "r"(b[0]), "r"(b[1]));
}
__device__ __forceinline__ void ldsm4(unsigned& r0, unsigned& r1, unsigned& r2, unsigned& r3,
                                      const void* p) {
    unsigned addr = (unsigned)__cvta_generic_to_shared(p);
    asm volatile("ldmatrix.sync.aligned.m8n8.x4.shared.b16 {%0,%1,%2,%3}, [%4];"
                 : "=r"(r0), "=r"(r1), "=r"(r2), "=r"(r3) : "r"(addr));
}
__device__ __forceinline__ void ldsm4t(unsigned& r0, unsigned& r1, unsigned& r2, unsigned& r3,
                                       const void* p) {
    unsigned addr = (unsigned)__cvta_generic_to_shared(p);
    asm volatile("ldmatrix.sync.aligned.m8n8.x4.trans.shared.b16 {%0,%1,%2,%3}, [%4];"
                 : "=r"(r0), "=r"(r1), "=r"(r2), "=r"(r3) : "r"(addr));
}
__device__ __forceinline__ void cpa16(void* dst, const void* src) {
    unsigned d = (unsigned)__cvta_generic_to_shared(dst);
    asm volatile("cp.async.cg.shared.global [%0], [%1], 16;" :: "r"(d), "l"(src));
}
__device__ __forceinline__ void cp_commit() { asm volatile("cp.async.commit_group;"); }

__device__ __forceinline__ unsigned pack_h2(float a, float b) {
    __half2 h = __floats2half2_rn(a, b);
    return *reinterpret_cast<unsigned*>(&h);
}

// ---------------------------------------------------------------------------
// fp32 -> fp16 conversion, 3 tensors in one launch
// ---------------------------------------------------------------------------
__device__ __forceinline__ void cvt8(const float* in, __half* out, int i) {
    float4 a = *reinterpret_cast<const float4*>(in + i);
    float4 b = *reinterpret_cast<const float4*>(in + i + 4);
    __half2 h[4] = { __floats2half2_rn(a.x, a.y), __floats2half2_rn(a.z, a.w),
                     __floats2half2_rn(b.x, b.y), __floats2half2_rn(b.z, b.w) };
    *reinterpret_cast<float4*>(out + i) = *reinterpret_cast<float4*>(h);
}

__global__ __launch_bounds__(256) void f2h3_kernel(
    const float* __restrict__ a, __half* __restrict__ oa, int na,
    const float* __restrict__ b, __half* __restrict__ ob, int nb,
    const float* __restrict__ c, __half* __restrict__ oc, int nc) {
    int i = (blockIdx.x * 256 + threadIdx.x) * 8;
    if (i < na)                cvt8(a, oa, i);
    else if (i < na + nb)      cvt8(b, ob, i - na);
    else if (i < na + nb + nc) cvt8(c, oc, i - na - nb);
}

// ---------------------------------------------------------------------------
// fp16 GEMM: CTA tile 256x128, BK=64, 2-stage cp.async, 512 threads
// (16 warps: 4m x 4n, warp tile 64x32). C[M,Nn] = A[M,K] @ B[K,Nn] + bias.
// mode 0: write float C. mode 1: scatter half into g_q/g_k/g_v.
// ---------------------------------------------------------------------------
#define GBM 256
#define GBK 64
#define GLDA 72
#define GLDB 136
#define GA_ST (GBM * GLDA)                 // halves per A stage
#define GB_ST (GBK * GLDB)                 // halves per B stage
#define GEMM_SMEM ((2 * GA_ST + 2 * GB_ST) * 2)   // 108544 B
#define QSCALE 0.1803368801111244f                 // 0.125 * log2(e)

__global__ __launch_bounds__(512) void gemm_f16(
    const __half* __restrict__ A, const __half* __restrict__ Bm,
    const float* __restrict__ bias, float* __restrict__ C,
    int Nn, int Kk, int mode)
{
    extern __shared__ __half gsm[];
    __half* As = gsm;                      // [2][256][GLDA]
    __half* Bs = gsm + 2 * GA_ST;          // [2][GBK][GLDB]

    int tid = threadIdx.x;
    int wid = tid >> 5, lane = tid & 31;
    int g = lane >> 2, t = lane & 3;
    int wm = wid & 3, wn = wid >> 2;       // 4m x 4n warp grid
    int bx = blockIdx.x, by = blockIdx.y;

    const __half* Ab = A + (size_t)by * GBM * Kk;
    const __half* Bb = Bm + (size_t)bx * 128;

    float acc[4][4][4];
    #pragma unroll
    for (int mi = 0; mi < 4; ++mi)
        #pragma unroll
        for (int ni = 0; ni < 4; ++ni)
            #pragma unroll
            for (int c = 0; c < 4; ++c) acc[mi][ni][c] = 0.f;

    int a_r = lane & 15, a_c8 = (lane >> 4) << 3;
    int b_r = ((lane >> 3) & 1) * 8 + (lane & 7);
    int b_c8 = (lane >> 4) << 3;

    // cp.async coords: A 256 rows x 8 chunks = 2048 (4/thr); B 64 x 16 = 1024 (2/thr)
    int ar[4], ac[4], br_[2], bc[2];
    #pragma unroll
    for (int it = 0; it < 4; ++it) {
        int idx = tid + it * 512;
        ar[it] = idx >> 3; ac[it] = (idx & 7) << 3;
    }
    #pragma unroll
    for (int it = 0; it < 2; ++it) {
        int idx = tid + it * 512;
        br_[it] = idx >> 4; bc[it] = (idx & 15) << 3;
    }

    const int nk = Kk / GBK;

    auto prefetch = [&](int kt) {
        int st = kt & 1;
        __half* Ad = As + st * GA_ST;
        __half* Bd = Bs + st * GB_ST;
        int k0 = kt * GBK;
        #pragma unroll
        for (int it = 0; it < 4; ++it)
            cpa16(&Ad[ar[it] * GLDA + ac[it]], Ab + (size_t)ar[it] * Kk + k0 + ac[it]);
        #pragma unroll
        for (int it = 0; it < 2; ++it)
            cpa16(&Bd[br_[it] * GLDB + bc[it]], Bb + (size_t)(k0 + br_[it]) * Nn + bc[it]);
        cp_commit();
    };

    prefetch(0);

    for (int kt = 0; kt < nk; ++kt) {
        int st = kt & 1;
        asm volatile("cp.async.wait_group 0;");
        __syncthreads();
        if (kt + 1 < nk) prefetch(kt + 1);

        const __half* Ac = As + st * GA_ST;
        const __half* Bc = Bs + st * GB_ST;
        #pragma unroll
        for (int ks = 0; ks < 4; ++ks) {
            int kk = ks * 16;
            unsigned a[4][4], b[4][2];
            #pragma unroll
            for (int mi = 0; mi < 4; ++mi)
                ldsm4(a[mi][0], a[mi][1], a[mi][2], a[mi][3],
                      &Ac[(wm * 64 + mi * 16 + a_r) * GLDA + kk + a_c8]);
            #pragma unroll
            for (int p = 0; p < 2; ++p) {
                unsigned r0, r1, r2, r3;
                ldsm4t(r0, r1, r2, r3, &Bc[(kk + b_r) * GLDB + wn * 32 + p * 16 + b_c8]);
                b[2 * p][0] = r0; b[2 * p][1] = r1;
                b[2 * p + 1][0] = r2; b[2 * p + 1][1] = r3;
            }
            #pragma unroll
            for (int mi = 0; mi < 4; ++mi)
                #pragma unroll
                for (int ni = 0; ni < 4; ++ni)
                    mma_f16(acc[mi][ni], a[mi], b[ni]);
        }
    }

    // Epilogue
    #pragma unroll
    for (int mi = 0; mi < 4; ++mi) {
        int r0 = by * GBM + wm * 64 + mi * 16 + g;
        #pragma unroll
        for (int ni = 0; ni < 4; ++ni) {
            int c0 = bx * 128 + wn * 32 + ni * 8 + t * 2;
            float bia0 = bias[c0], bia1 = bias[c0 + 1];
            float v00 = acc[mi][ni][0] + bia0;
            float v01 = acc[mi][ni][1] + bia1;
            float v10 = acc[mi][ni][2] + bia0;
            float v11 = acc[mi][ni][3] + bia1;
            if (mode == 0) {
                C[(size_t)r0 * Nn + c0]           = v00;
                C[(size_t)r0 * Nn + c0 + 1]       = v01;
                C[(size_t)(r0 + 8) * Nn + c0]     = v10;
                C[(size_t)(r0 + 8) * Nn + c0 + 1] = v11;
            } else {
                // half2 scatter: c0, c0+1 are same (which, head); d0 even
                int which = c0 >> 10, h = c0 & 1023;
                int hn = h >> 6, d0 = h & 63;
                __half* base = (which == 0 ? g_q : which == 1 ? g_k : g_v);
                float sc = (which == 0) ? QSCALE : 1.0f;
                #pragma unroll
                for (int e = 0; e < 2; ++e) {
                    int rr = r0 + e * 8;
                    int b_ = rr >> 11, s_ = rr & 2047;
                    __half* dst = base + ((size_t)(b_ * NH + hn) * SS + s_) * HD + d0;
                    float va = (e == 0) ? v00 : v10;
                    float vb = (e == 0) ? v01 : v11;
                    *reinterpret_cast<__half2*>(dst) = __floats2half2_rn(va * sc, vb * sc);
                }
            }
        }
    }
}

// ---------------------------------------------------------------------------
// Causal flash attention (R10-proven config): fp16 mma.sync, FA2 register
// P-reuse, hoisted Q frags, exp2 softmax (log2e folded into q pre-scale).
// CTA: 128 threads (4 warps), 64 q-rows, 64-key tiles, cp.async dbl-buffered.
// smem: Qs[64][72], Ks[2][64][72], Vs[2][64][72] = 46080 B.
// ---------------------------------------------------------------------------
#define ALD 72
#define AT_ST (64 * ALD)
#define ATTN_SMEM (5 * AT_ST * 2)

__global__ __launch_bounds__(128) void attn_f16() {
    extern __shared__ __half asm_[];
    __half* Qs = asm_;
    __half* Ks = asm_ + AT_ST;             // [2][64][ALD]
    __half* Vs = asm_ + 3 * AT_ST;         // [2][64][ALD]

    int qb = (gridDim.x - 1) - blockIdx.x; // heavy q-blocks launch first
    int bn = blockIdx.y;
    const __half* Qp = g_q + (size_t)bn * SS * HD;
    const __half* Kp = g_k + (size_t)bn * SS * HD;
    const __half* Vp = g_v + (size_t)bn * SS * HD;

    int tid = threadIdx.x;
    int wid = tid >> 5, lane = tid & 31;
    int g = lane >> 2, t = lane & 3;
    int row0 = wid * 16;

    int a_r = lane & 15, a_c8 = (lane >> 4) << 3;
    int kb_r = ((lane >> 4) & 1) * 8 + (lane & 7);
    int kb_c8 = ((lane >> 3) & 1) * 8;
    int vb_r = ((lane >> 3) & 1) * 8 + (lane & 7);
    int vb_c8 = (lane >> 4) << 3;

    int cr[4], cc_[4];
    #pragma unroll
    for (int it = 0; it < 4; ++it) {
        int idx = tid + it * 128;
        cr[it] = idx >> 3; cc_[it] = (idx & 7) << 3;
    }

    auto prefetch_kv = [&](int j) {
        int st = j & 1;
        const __half* Kn = Kp + (size_t)j * 64 * HD;
        const __half* Vn = Vp + (size_t)j * 64 * HD;
        __half* Kd = Ks + st * AT_ST;
        __half* Vd = Vs + st * AT_ST;
        #pragma unroll
        for (int it = 0; it < 4; ++it) {
            cpa16(&Kd[cr[it] * ALD + cc_[it]], Kn + (size_t)cr[it] * HD + cc_[it]);
            cpa16(&Vd[cr[it] * ALD + cc_[it]], Vn + (size_t)cr[it] * HD + cc_[it]);
        }
        cp_commit();
    };

    prefetch_kv(0);

    // Q tile (plain loads, overlap with prefetch)
    #pragma unroll
    for (int it = 0; it < 4; ++it) {
        float4 v = *reinterpret_cast<const float4*>(Qp + (size_t)(qb * 64 + cr[it]) * HD + cc_[it]);
        *reinterpret_cast<float4*>(&Qs[cr[it] * ALD + cc_[it]]) = v;
    }
    __syncthreads();

    // Hoist Q fragments (constant across all KV tiles)
    unsigned qa[4][4];
    #pragma unroll
    for (int ks = 0; ks < 4; ++ks)
        ldsm4(qa[ks][0], qa[ks][1], qa[ks][2], qa[ks][3],
              &Qs[(row0 + a_r) * ALD + ks * 16 + a_c8]);

    float accO[8][4];
    #pragma unroll
    for (int ni = 0; ni < 8; ++ni)
        #pragma unroll
        for (int c = 0; c < 4; ++c) accO[ni][c] = 0.f;
    float mr0 = -1e30f, mr1 = -1e30f, lr0 = 0.f, lr1 = 0.f;

    for (int j = 0; j <= qb; ++j) {
        int st = j & 1;
        asm volatile("cp.async.wait_group 0;");
        __syncthreads();
        if (j < qb) prefetch_kv(j + 1);

        const __half* Kc = Ks + st * AT_ST;
        const __half* Vc = Vs + st * AT_ST;

        // S = Q @ K^T
        float s[8][4];
        #pragma unroll
        for (int ni = 0; ni < 8; ++ni)
            #pragma unroll
            for (int c = 0; c < 4; ++c) s[ni][c] = 0.f;

        #pragma unroll
        for (int ks = 0; ks < 4; ++ks) {
            int kk = ks * 16;
            #pragma unroll
            for (int p = 0; p < 4; ++p) {
                unsigned r0, r1, r2, r3;
                ldsm4(r0, r1, r2, r3, &Kc[(p * 16 + kb_r) * ALD + kk + kb_c8]);
                unsigned b0[2] = {r0, r1}, b1[2] = {r2, r3};
                mma_f16(s[2 * p], qa[ks], b0);
                mma_f16(s[2 * p + 1], qa[ks], b1);
            }
        }

        if (j == qb) {
            #pragma unroll
            for (int ni = 0; ni < 8; ++ni) {
                int c0 = ni * 8 + t * 2;
                int r0a = row0 + g, r1a = r0a + 8;
                if (c0     > r0a) s[ni][0] = -1e30f;
                if (c0 + 1 > r0a) s[ni][1] = -1e30f;
                if (c0     > r1a) s[ni][2] = -1e30f;
                if (c0 + 1 > r1a) s[ni][3] = -1e30f;
            }
        }

        // online softmax (base-2; log2e folded into q)
        float mx0 = -1e30f, mx1 = -1e30f;
        #pragma unroll
        for (int ni = 0; ni < 8; ++ni) {
            mx0 = fmaxf(mx0, fmaxf(s[ni][0], s[ni][1]));
            mx1 = fmaxf(mx1, fmaxf(s[ni][2], s[ni][3]));
        }
        mx0 = fmaxf(mx0, __shfl_xor_sync(0xffffffffu, mx0, 1));
        mx0 = fmaxf(mx0, __shfl_xor_sync(0xffffffffu, mx0, 2));
        mx1 = fmaxf(mx1, __shfl_xor_sync(0xffffffffu, mx1, 1));
        mx1 = fmaxf(mx1, __shfl_xor_sync(0xffffffffu, mx1, 2));

        float mn0 = fmaxf(mr0, mx0), mn1 = fmaxf(mr1, mx1);
        float corr0 = exp2f(mr0 - mn0), corr1 = exp2f(mr1 - mn1);
        float sum0 = 0.f, sum1 = 0.f;
        #pragma unroll
        for (int ni = 0; ni < 8; ++ni) {
            s[ni][0] = exp2f(s[ni][0] - mn0);
            s[ni][1] = exp2f(s[ni][1] - mn0);
            s[ni][2] = exp2f(s[ni][2] - mn1);
            s[ni][3] = exp2f(s[ni][3] - mn1);
            sum0 += s[ni][0] + s[ni][1];
            sum1 += s[ni][2] + s[ni][3];
        }
        sum0 += __shfl_xor_sync(0xffffffffu, sum0, 1);
        sum0 += __shfl_xor_sync(0xffffffffu, sum0, 2);
        sum1 += __shfl_xor_sync(0xffffffffu, sum1, 1);
        sum1 += __shfl_xor_sync(0xffffffffu, sum1, 2);
        lr0 = lr0 * corr0 + sum0;
        lr1 = lr1 * corr1 + sum1;
        mr0 = mn0; mr1 = mn1;
        #pragma unroll
        for (int ni = 0; ni < 8; ++ni) {
            accO[ni][0] *= corr0; accO[ni][1] *= corr0;
            accO[ni][2] *= corr1; accO[ni][3] *= corr1;
        }

        // O += P @ V (register P, FA2 layout reuse)
        #pragma unroll
        for (int p = 0; p < 4; ++p) {
            unsigned pa[4];
            pa[0] = pack_h2(s[2 * p][0],     s[2 * p][1]);
            pa[1] = pack_h2(s[2 * p][2],     s[2 * p][3]);
            pa[2] = pack_h2(s[2 * p + 1][0], s[2 * p + 1][1]);
            pa[3] = pack_h2(s[2 * p + 1][2], s[2 * p + 1][3]);
            int kk = p * 16;
            #pragma unroll
            for (int q = 0; q < 4; ++q) {
                unsigned r0, r1, r2, r3;
                ldsm4t(r0, r1, r2, r3, &Vc[(kk + vb_r) * ALD + q * 16 + vb_c8]);
                unsigned b0[2] = {r0, r1}, b1[2] = {r2, r3};
                mma_f16(accO[2 * q], pa, b0);
                mma_f16(accO[2 * q + 1], pa, b1);
            }
        }
    }

    // Finalize: write ctx (half) in [b*s, h] layout
    int b_ = bn >> 4, n = bn & 15;
    float inv0 = 1.0f / lr0, inv1 = 1.0f / lr1;
    int s0 = qb * 64 + row0 + g;
    int s1 = s0 + 8;
    #pragma unroll
    for (int ni = 0; ni < 8; ++ni) {
        int c0 = n * HD + ni * 8 + t * 2;
        *reinterpret_cast<__half2*>(&g_ctx[((size_t)b_ * SS + s0) * HH + c0]) =
            __floats2half2_rn(accO[ni][0] * inv0, accO[ni][1] * inv0);
        *reinterpret_cast<__half2*>(&g_ctx[((size_t)b_ * SS + s1) * HH + c0]) =
            __floats2half2_rn(accO[ni][2] * inv1, accO[ni][3] * inv1);
    }
}

// ---------------------------------------------------------------------------
extern "C" void kernel_launch(void* const* d_in, const int* in_sizes, int n_in,
                              void* d_out, int out_size) {
    const float* hs      = (const float*)d_in[0];
    const float* w_qkv   = (const float*)d_in[2];
    const float* b_qkv   = (const float*)d_in[3];
    const float* w_dense = (const float*)d_in[4];
    const float* b_dense = (const float*)d_in[5];
    float* out = (float*)d_out;

    void *hs_h, *wqkv_h, *wd_h, *ctx_h;
    cudaGetSymbolAddress(&hs_h, g_hs);
    cudaGetSymbolAddress(&wqkv_h, g_wqkv);
    cudaGetSymbolAddress(&wd_h, g_wd);
    cudaGetSymbolAddress(&ctx_h, g_ctx);

    cudaFuncSetAttribute(gemm_f16, cudaFuncAttributeMaxDynamicSharedMemorySize, GEMM_SMEM);
    cudaFuncSetAttribute(attn_f16, cudaFuncAttributeMaxDynamicSharedMemorySize, ATTN_SMEM);

    // 0) fp32 -> fp16 conversions (single launch for all three tensors)
    const int n1 = MROWS * HH, n2 = HH * QKV_N, n3 = HH * HH;
    f2h3_kernel<<<(n1 + n2 + n3) / (256 * 8), 256>>>(
        hs, (__half*)hs_h, n1, w_qkv, (__half*)wqkv_h, n2, w_dense, (__half*)wd_h, n3);

    // 1) QKV projection with head-layout scatter (q pre-scaled by 0.125*log2e)
    dim3 g1(QKV_N / 128, MROWS / GBM);   // (24, 16)
    gemm_f16<<<g1, 512, GEMM_SMEM>>>((const __half*)hs_h, (const __half*)wqkv_h,
                                     b_qkv, nullptr, QKV_N, HH, 1);

    // 2) Causal flash attention
    dim3 g2(SS / 64, BB * NH);           // (32, 32)
    attn_f16<<<g2, 128, ATTN_SMEM>>>();

    // 3) Output projection
    dim3 g3(HH / 128, MROWS / GBM);      // (8, 16)
    gemm_f16<<<g3, 512, GEMM_SMEM>>>((const __half*)ctx_h, (const __half*)wd_h,
                                     b_dense, out, HH, HH, 0);
}